// round 3
// baseline (speedup 1.0000x reference)
#include <cuda_runtime.h>
#include <math.h>

// Problem shape (fixed by the dataset): encoder_output [C,K,H] fp32, W [H,H] fp32.
#define C_DIM 512
#define K_DIM 64
#define H_DIM 1024
#define H4 (H_DIM / 4)   // 256 float4 per H row

// -------------------------------------------------------------------------
// Scratch (device globals only — no runtime allocation allowed)
// -------------------------------------------------------------------------
__device__ __align__(16) float g_s [C_DIM * H_DIM];  // weighted sums   s[c,h]
__device__ __align__(16) float g_c [C_DIM * H_DIM];  // squashed caps   c[c,h]
__device__ __align__(16) float g_p0[C_DIM * H_DIM];  // GEMM split-K partial 0
__device__ __align__(16) float g_p1[C_DIM * H_DIM];  // GEMM split-K partial 1
__device__ __align__(16) float g_b [C_DIM * K_DIM];  // routing logits  b[c,k]

// -------------------------------------------------------------------------
// Kernel 1: iteration-1 weighted sum with uniform d = 1/64, and b <- 0.
// grid = 512 (capsule), block = 256, each thread owns 4 h via float4.
// -------------------------------------------------------------------------
__global__ __launch_bounds__(256) void ws_uniform_kernel(const float* __restrict__ x) {
    const int c = blockIdx.x;
    const int t = threadIdx.x;
    const float4* xp = reinterpret_cast<const float4*>(x) + (size_t)c * K_DIM * H4;

    float4 acc = make_float4(0.f, 0.f, 0.f, 0.f);
#pragma unroll 8
    for (int k = 0; k < K_DIM; ++k) {
        float4 v = __ldg(&xp[k * H4 + t]);
        acc.x += v.x; acc.y += v.y; acc.z += v.z; acc.w += v.w;
    }
    const float inv = 1.0f / (float)K_DIM;
    float4 o = make_float4(acc.x * inv, acc.y * inv, acc.z * inv, acc.w * inv);
    reinterpret_cast<float4*>(g_s)[c * H4 + t] = o;

    if (t < K_DIM) g_b[c * K_DIM + t] = 0.0f;
}

// -------------------------------------------------------------------------
// SIMT fp32 GEMM, out[m,n] = sum_k A[m,k] * (BT ? B[n,k] : B[k,n])
// M=512, N=1024, K=1024. BM=BN=64, BK=16, 4x4/thread, 256 threads.
// Split-K=2 over blockIdx.z -> partials in g_p0/g_p1 (combined by consumer).
//   BT=1 : c_hat = s @ W^T   (reduce over h, both operands row-contiguous in k)
//   BT=0 : t     = c @ W     (reduce over o, B rows contiguous in n)
// -------------------------------------------------------------------------
template <int BT>
__global__ __launch_bounds__(256) void gemm64_kernel(const float* __restrict__ A,
                                                     const float* __restrict__ B,
                                                     float* __restrict__ P0,
                                                     float* __restrict__ P1) {
    __shared__ __align__(16) float As[16][64];
    __shared__ __align__(16) float Bs[16][64];

    const int tid  = threadIdx.x;
    const int m0   = blockIdx.y * 64;
    const int n0   = blockIdx.x * 64;
    const int kbeg = blockIdx.z * 512;

    const int tm = (tid >> 4) * 4;   // 0..60, row offset in tile
    const int tn = (tid & 15) * 4;   // 0..60, col offset in tile

    const int row = tid >> 2;        // 0..63  (A / B-transposed loads)
    const int cg  = tid & 3;         // 0..3   (k group)
    const int krow = tid >> 4;       // 0..15  (B row-major loads)
    const int ncg  = tid & 15;       // 0..15

    float acc[4][4];
#pragma unroll
    for (int i = 0; i < 4; ++i)
#pragma unroll
        for (int j = 0; j < 4; ++j) acc[i][j] = 0.f;

    for (int kb = 0; kb < 512; kb += 16) {
        const int k0 = kbeg + kb;

        // A tile: rows m0..m0+63, k0..k0+15, stored transposed As[k][m]
        float4 av = *reinterpret_cast<const float4*>(&A[(m0 + row) * H_DIM + k0 + cg * 4]);
        As[cg * 4 + 0][row] = av.x;
        As[cg * 4 + 1][row] = av.y;
        As[cg * 4 + 2][row] = av.z;
        As[cg * 4 + 3][row] = av.w;

        if (BT) {
            // B[n,k]: rows n0..n0+63, k contiguous -> transpose into Bs[k][n]
            float4 bv = *reinterpret_cast<const float4*>(&B[(n0 + row) * H_DIM + k0 + cg * 4]);
            Bs[cg * 4 + 0][row] = bv.x;
            Bs[cg * 4 + 1][row] = bv.y;
            Bs[cg * 4 + 2][row] = bv.z;
            Bs[cg * 4 + 3][row] = bv.w;
        } else {
            // B[k,n]: 16 rows x 64 cols, n contiguous -> direct Bs[k][n]
            float4 bv = *reinterpret_cast<const float4*>(&B[(k0 + krow) * H_DIM + n0 + ncg * 4]);
            *reinterpret_cast<float4*>(&Bs[krow][ncg * 4]) = bv;
        }
        __syncthreads();

#pragma unroll
        for (int kk = 0; kk < 16; ++kk) {
            float4 a4 = *reinterpret_cast<const float4*>(&As[kk][tm]);
            float4 b4 = *reinterpret_cast<const float4*>(&Bs[kk][tn]);
            float ar[4] = {a4.x, a4.y, a4.z, a4.w};
            float br[4] = {b4.x, b4.y, b4.z, b4.w};
#pragma unroll
            for (int i = 0; i < 4; ++i)
#pragma unroll
                for (int j = 0; j < 4; ++j) acc[i][j] += ar[i] * br[j];
        }
        __syncthreads();
    }

    float* P = (blockIdx.z == 0) ? P0 : P1;
#pragma unroll
    for (int i = 0; i < 4; ++i) {
        float4 o = make_float4(acc[i][0], acc[i][1], acc[i][2], acc[i][3]);
        *reinterpret_cast<float4*>(&P[(m0 + tm + i) * H_DIM + n0 + tn]) = o;
    }
}

// -------------------------------------------------------------------------
// Squash: v = p0+p1 (split-K combine); out = v * (ns/(1+ns)) / sqrt(ns+eps)
// grid = 512, block = 256 (4 h per thread).
// -------------------------------------------------------------------------
__global__ __launch_bounds__(256) void squash_kernel(float* __restrict__ outp) {
    const int c = blockIdx.x;
    const int t = threadIdx.x;
    const int lane = t & 31, wid = t >> 5;

    const float4* p0 = reinterpret_cast<const float4*>(g_p0);
    const float4* p1 = reinterpret_cast<const float4*>(g_p1);
    float4 a = p0[c * H4 + t];
    float4 b = p1[c * H4 + t];
    float4 v = make_float4(a.x + b.x, a.y + b.y, a.z + b.z, a.w + b.w);

    float p = v.x * v.x + v.y * v.y + v.z * v.z + v.w * v.w;
#pragma unroll
    for (int off = 16; off; off >>= 1) p += __shfl_down_sync(0xffffffffu, p, off);

    __shared__ float wsum[8];
    if (lane == 0) wsum[wid] = p;
    __syncthreads();
    float ns = 0.f;
#pragma unroll
    for (int w = 0; w < 8; ++w) ns += wsum[w];  // identical order in all threads

    const float scale = (ns / (1.0f + ns)) * rsqrtf(ns + 1e-9f);
    float4 o = make_float4(v.x * scale, v.y * scale, v.z * scale, v.w * scale);
    reinterpret_cast<float4*>(outp)[c * H4 + t] = o;
}

// -------------------------------------------------------------------------
// Fused routing step for iterations 2..3:
//   t = p0+p1 (split-K combine of c@W)
//   b[c,k] += sum_h x[c,k,h] * t[c,h]   (phase A, block reduce per k)
//   d = softmax(b)                       (warp 0)
//   s[c,h] = sum_k d[c,k] * x[c,k,h]    (phase B, x re-read hits L1/L2)
// grid = 512 (capsule), block = 256.
// -------------------------------------------------------------------------
__global__ __launch_bounds__(256) void fused_route_kernel(const float* __restrict__ x) {
    const int c = blockIdx.x;
    const int t = threadIdx.x;
    const int lane = t & 31, wid = t >> 5;

    __shared__ float wsum[K_DIM][8];
    __shared__ float bsh[K_DIM];
    __shared__ float dsh[K_DIM];

    const float4* p0 = reinterpret_cast<const float4*>(g_p0);
    const float4* p1 = reinterpret_cast<const float4*>(g_p1);
    float4 ta = p0[c * H4 + t];
    float4 tb = p1[c * H4 + t];
    const float4 tv = make_float4(ta.x + tb.x, ta.y + tb.y, ta.z + tb.z, ta.w + tb.w);

    const float4* xp = reinterpret_cast<const float4*>(x) + (size_t)c * K_DIM * H4;

    // ---- Phase A: agreement b_inc[k] ----
#pragma unroll 4
    for (int k = 0; k < K_DIM; ++k) {
        float4 xv = __ldg(&xp[k * H4 + t]);
        float p = xv.x * tv.x + xv.y * tv.y + xv.z * tv.z + xv.w * tv.w;
#pragma unroll
        for (int off = 16; off; off >>= 1) p += __shfl_down_sync(0xffffffffu, p, off);
        if (lane == 0) wsum[k][wid] = p;
    }
    __syncthreads();

    if (t < K_DIM) {
        float bb = g_b[c * K_DIM + t];
#pragma unroll
        for (int w = 0; w < 8; ++w) bb += wsum[t][w];
        g_b[c * K_DIM + t] = bb;
        bsh[t] = bb;
    }
    __syncthreads();

    // ---- Softmax over K=64 in warp 0 (2 elements per lane) ----
    if (t < 32) {
        float b0 = bsh[t], b1 = bsh[t + 32];
        float m = fmaxf(b0, b1);
#pragma unroll
        for (int off = 16; off; off >>= 1) m = fmaxf(m, __shfl_xor_sync(0xffffffffu, m, off));
        float e0 = expf(b0 - m), e1 = expf(b1 - m);
        float ss = e0 + e1;
#pragma unroll
        for (int off = 16; off; off >>= 1) ss += __shfl_xor_sync(0xffffffffu, ss, off);
        float inv = 1.0f / ss;
        dsh[t]      = e0 * inv;
        dsh[t + 32] = e1 * inv;
    }
    __syncthreads();

    // ---- Phase B: weighted sum (x re-read, L1/L2-resident) ----
    float4 acc = make_float4(0.f, 0.f, 0.f, 0.f);
#pragma unroll 4
    for (int k = 0; k < K_DIM; ++k) {
        const float dk = dsh[k];
        float4 xv = xp[k * H4 + t];
        acc.x += dk * xv.x; acc.y += dk * xv.y;
        acc.z += dk * xv.z; acc.w += dk * xv.w;
    }
    reinterpret_cast<float4*>(g_s)[c * H4 + t] = acc;
}

// -------------------------------------------------------------------------
// Launch: 3 routing iterations.
//   iter i:  gemmA (s @ W^T) -> squash -> c_i
//            if i < 3:  gemmB (c_i @ W) -> fused (b update, softmax, new s)
// Output = c_3 (squash of final iteration writes d_out directly).
// -------------------------------------------------------------------------
extern "C" void kernel_launch(void* const* d_in, const int* in_sizes, int n_in,
                              void* d_out, int out_size) {
    const float* x = (const float*)d_in[0];   // [C,K,H] = [512,64,1024]
    const float* W = (const float*)d_in[1];   // [H,H]   = [1024,1024]
    float* out = (float*)d_out;               // [C,H]   = [512,1024]

    float *s_ptr, *c_ptr, *p0_ptr, *p1_ptr;
    cudaGetSymbolAddress((void**)&s_ptr,  g_s);
    cudaGetSymbolAddress((void**)&c_ptr,  g_c);
    cudaGetSymbolAddress((void**)&p0_ptr, g_p0);
    cudaGetSymbolAddress((void**)&p1_ptr, g_p1);

    const dim3 gemm_grid(H_DIM / 64, C_DIM / 64, 2);  // (16, 8, 2)

    // iteration 1: uniform d, zero b
    ws_uniform_kernel<<<C_DIM, 256>>>(x);

    for (int iter = 0; iter < 3; ++iter) {
        // c_hat = s @ W^T  (split-K partials)
        gemm64_kernel<1><<<gemm_grid, 256>>>(s_ptr, W, p0_ptr, p1_ptr);
        // combine + squash -> c (final iteration writes the output directly)
        squash_kernel<<<C_DIM, 256>>>(iter == 2 ? out : c_ptr);

        if (iter < 2) {
            // t = c @ W  (split-K partials)
            gemm64_kernel<0><<<gemm_grid, 256>>>(c_ptr, W, p0_ptr, p1_ptr);
            // b += x.t ; d = softmax(b) ; s = sum_k d*x
            fused_route_kernel<<<C_DIM, 256>>>(x);
        }
    }
}

// round 4
// speedup vs baseline: 1.4110x; 1.4110x over previous
#include <cuda_runtime.h>
#include <math.h>

// Problem shape (fixed): encoder_output [C,K,H] fp32, W [H,H] fp32.
#define C_DIM 512
#define K_DIM 64
#define H_DIM 1024
#define H4 (H_DIM / 4)

// GEMM config: M=512, N=1024, K=1024. CTA tile 128x128, BK=16, split-K=4.
#define SPLITK 4
#define KSEG (H_DIM / SPLITK)   // 256 per CTA
#define NITER (KSEG / 16)       // 16 BK iterations

// -------------------------------------------------------------------------
// Scratch (device globals only)
// -------------------------------------------------------------------------
__device__ __align__(16) float g_s [C_DIM * H_DIM];          // weighted sums
__device__ __align__(16) float g_c [C_DIM * H_DIM];          // squashed caps
__device__ __align__(16) float g_part[SPLITK][C_DIM * H_DIM];// split-K partials
__device__ __align__(16) float g_b [C_DIM * K_DIM];          // routing logits

// -------------------------------------------------------------------------
// PTX helpers
// -------------------------------------------------------------------------
__device__ __forceinline__ unsigned cvt_tf32(float x) {
    unsigned r;
    asm("cvt.rna.tf32.f32 %0, %1;" : "=r"(r) : "f"(x));
    return r;
}

__device__ __forceinline__ void mma_tf32(float c[4],
                                         unsigned a0, unsigned a1, unsigned a2, unsigned a3,
                                         unsigned b0, unsigned b1) {
    asm volatile(
        "mma.sync.aligned.m16n8k8.row.col.f32.tf32.tf32.f32 "
        "{%0,%1,%2,%3}, {%4,%5,%6,%7}, {%8,%9}, {%0,%1,%2,%3};"
        : "+f"(c[0]), "+f"(c[1]), "+f"(c[2]), "+f"(c[3])
        : "r"(a0), "r"(a1), "r"(a2), "r"(a3), "r"(b0), "r"(b1));
}

__device__ __forceinline__ void cp16(void* smem, const void* gmem) {
    unsigned s = (unsigned)__cvta_generic_to_shared(smem);
    asm volatile("cp.async.cg.shared.global [%0], [%1], 16;" :: "r"(s), "l"(gmem));
}
__device__ __forceinline__ void cp_commit() { asm volatile("cp.async.commit_group;"); }
__device__ __forceinline__ void cp_wait0()  { asm volatile("cp.async.wait_group 0;" ::: "memory"); }

// -------------------------------------------------------------------------
// Kernel 1: iteration-1 weighted sum with uniform d = 1/64, and b <- 0.
// -------------------------------------------------------------------------
__global__ __launch_bounds__(256) void ws_uniform_kernel(const float* __restrict__ x) {
    const int c = blockIdx.x;
    const int t = threadIdx.x;
    const float4* xp = reinterpret_cast<const float4*>(x) + (size_t)c * K_DIM * H4;

    float4 acc = make_float4(0.f, 0.f, 0.f, 0.f);
#pragma unroll 8
    for (int k = 0; k < K_DIM; ++k) {
        float4 v = __ldg(&xp[k * H4 + t]);
        acc.x += v.x; acc.y += v.y; acc.z += v.z; acc.w += v.w;
    }
    const float inv = 1.0f / (float)K_DIM;
    reinterpret_cast<float4*>(g_s)[c * H4 + t] =
        make_float4(acc.x * inv, acc.y * inv, acc.z * inv, acc.w * inv);

    if (t < K_DIM) g_b[c * K_DIM + t] = 0.0f;
}

// -------------------------------------------------------------------------
// Tensor-core 3xTF32 GEMM: out[m,n] = sum_k A[m,k] * (BT ? B[n,k] : B[k,n])
// CTA 128x128, BK=16, 128 threads (4 warps, 2x2 grid, 64x64 warp tiles).
// Split-K over blockIdx.z -> g_part[z]. Double-buffered cp.async pipeline.
// -------------------------------------------------------------------------
template <int BT>
__global__ __launch_bounds__(128, 1) void gemm_tc_kernel(const float* __restrict__ A,
                                                         const float* __restrict__ B,
                                                         float* __restrict__ part_base) {
    constexpr int AS   = 20;                       // A smem row stride (floats), 20 % 8 == 4
    constexpr int BSEL = BT ? (128 * 20) : (16 * 136);
    __shared__ __align__(16) float sA[2][128 * AS];
    __shared__ __align__(16) float sB[2][BSEL];

    const int tid  = threadIdx.x;
    const int w    = tid >> 5, lane = tid & 31;
    const int g    = lane >> 2, tig = lane & 3;
    const int wm   = w >> 1, wn = w & 1;
    const int m0   = blockIdx.y * 128;
    const int n0   = blockIdx.x * 128;
    const int kbeg = blockIdx.z * KSEG;

    float acc[4][8][4];
#pragma unroll
    for (int i = 0; i < 4; ++i)
#pragma unroll
        for (int j = 0; j < 8; ++j)
#pragma unroll
            for (int q = 0; q < 4; ++q) acc[i][j][q] = 0.f;

    auto issue = [&](int it, int buf) {
        const int kw = kbeg + it * 16;
        {   // A tile: 128 rows x 16 floats
            const int f = tid & 3, r0 = tid >> 2;
#pragma unroll
            for (int rr = 0; rr < 4; ++rr) {
                const int row = r0 + rr * 32;
                cp16(&sA[buf][row * AS + f * 4],
                     A + (size_t)(m0 + row) * H_DIM + kw + f * 4);
            }
        }
        if (BT) {   // B[n,k]: 128 rows (n) x 16 floats (k) -> sB[n][k], stride 20
            const int f = tid & 3, r0 = tid >> 2;
#pragma unroll
            for (int rr = 0; rr < 4; ++rr) {
                const int row = r0 + rr * 32;
                cp16(&sB[buf][row * 20 + f * 4],
                     B + (size_t)(n0 + row) * H_DIM + kw + f * 4);
            }
        } else {    // B[k,n]: 16 rows (k) x 128 floats (n) -> sB[k][n], stride 136
            const int f = tid & 31, r0 = tid >> 5;
#pragma unroll
            for (int rr = 0; rr < 4; ++rr) {
                const int row = r0 + rr * 4;
                cp16(&sB[buf][row * 136 + f * 4],
                     B + (size_t)(kw + row) * H_DIM + n0 + f * 4);
            }
        }
        cp_commit();
    };

    issue(0, 0);
    int buf = 0;
    for (int it = 0; it < NITER; ++it) {
        cp_wait0();
        __syncthreads();
        if (it + 1 < NITER) issue(it + 1, buf ^ 1);

        const float* a_s = sA[buf];
        const float* b_s = sB[buf];
#pragma unroll
        for (int ks = 0; ks < 16; ks += 8) {
            // A fragments for 4 m-tiles, split hi/lo in-register
            unsigned ahi[4][4], alo[4][4];
#pragma unroll
            for (int i = 0; i < 4; ++i) {
                const int m = wm * 64 + i * 16;
                float x0 = a_s[(m + g)     * AS + ks + tig];
                float x1 = a_s[(m + g + 8) * AS + ks + tig];
                float x2 = a_s[(m + g)     * AS + ks + tig + 4];
                float x3 = a_s[(m + g + 8) * AS + ks + tig + 4];
                ahi[i][0] = cvt_tf32(x0); alo[i][0] = cvt_tf32(x0 - __uint_as_float(ahi[i][0]));
                ahi[i][1] = cvt_tf32(x1); alo[i][1] = cvt_tf32(x1 - __uint_as_float(ahi[i][1]));
                ahi[i][2] = cvt_tf32(x2); alo[i][2] = cvt_tf32(x2 - __uint_as_float(ahi[i][2]));
                ahi[i][3] = cvt_tf32(x3); alo[i][3] = cvt_tf32(x3 - __uint_as_float(ahi[i][3]));
            }
#pragma unroll
            for (int j = 0; j < 8; ++j) {
                const int n = wn * 64 + j * 8;
                float y0, y1;
                if (BT) {
                    y0 = b_s[(n + g) * 20 + ks + tig];
                    y1 = b_s[(n + g) * 20 + ks + tig + 4];
                } else {
                    y0 = b_s[(ks + tig)     * 136 + n + g];
                    y1 = b_s[(ks + tig + 4) * 136 + n + g];
                }
                unsigned bh0 = cvt_tf32(y0), bl0 = cvt_tf32(y0 - __uint_as_float(bh0));
                unsigned bh1 = cvt_tf32(y1), bl1 = cvt_tf32(y1 - __uint_as_float(bh1));
#pragma unroll
                for (int i = 0; i < 4; ++i) {
                    mma_tf32(acc[i][j], ahi[i][0], ahi[i][1], ahi[i][2], ahi[i][3], bh0, bh1);
                    mma_tf32(acc[i][j], ahi[i][0], ahi[i][1], ahi[i][2], ahi[i][3], bl0, bl1);
                    mma_tf32(acc[i][j], alo[i][0], alo[i][1], alo[i][2], alo[i][3], bh0, bh1);
                }
            }
        }
        buf ^= 1;
    }

    // Epilogue: write 128x128 partial tile to g_part[z]
    float* P = part_base + (size_t)blockIdx.z * (C_DIM * H_DIM);
#pragma unroll
    for (int i = 0; i < 4; ++i) {
        const int m = m0 + wm * 64 + i * 16;
#pragma unroll
        for (int j = 0; j < 8; ++j) {
            const int n = n0 + wn * 64 + j * 8 + 2 * tig;
            *reinterpret_cast<float2*>(&P[(size_t)(m + g)     * H_DIM + n]) =
                make_float2(acc[i][j][0], acc[i][j][1]);
            *reinterpret_cast<float2*>(&P[(size_t)(m + g + 8) * H_DIM + n]) =
                make_float2(acc[i][j][2], acc[i][j][3]);
        }
    }
}

// -------------------------------------------------------------------------
// Squash: v = sum of SPLITK partials; out = v * (ns/(1+ns)) / sqrt(ns+eps)
// -------------------------------------------------------------------------
__global__ __launch_bounds__(256) void squash_kernel(float* __restrict__ outp) {
    const int c = blockIdx.x;
    const int t = threadIdx.x;
    const int lane = t & 31, wid = t >> 5;

    float4 v = make_float4(0.f, 0.f, 0.f, 0.f);
#pragma unroll
    for (int z = 0; z < SPLITK; ++z) {
        float4 a = reinterpret_cast<const float4*>(g_part[z])[c * H4 + t];
        v.x += a.x; v.y += a.y; v.z += a.z; v.w += a.w;
    }

    float p = v.x * v.x + v.y * v.y + v.z * v.z + v.w * v.w;
#pragma unroll
    for (int off = 16; off; off >>= 1) p += __shfl_down_sync(0xffffffffu, p, off);

    __shared__ float wsum[8];
    if (lane == 0) wsum[wid] = p;
    __syncthreads();
    float ns = 0.f;
#pragma unroll
    for (int wq = 0; wq < 8; ++wq) ns += wsum[wq];

    const float scale = (ns / (1.0f + ns)) * rsqrtf(ns + 1e-9f);
    reinterpret_cast<float4*>(outp)[c * H4 + t] =
        make_float4(v.x * scale, v.y * scale, v.z * scale, v.w * scale);
}

// -------------------------------------------------------------------------
// Fused routing step:
//   t = sum of partials (c@W split-K combine)
//   b[c,k] += x[c,k,:].t ; d = softmax(b) ; s[c,:] = sum_k d[k]*x[c,k,:]
// -------------------------------------------------------------------------
__global__ __launch_bounds__(256) void fused_route_kernel(const float* __restrict__ x) {
    const int c = blockIdx.x;
    const int t = threadIdx.x;
    const int lane = t & 31, wid = t >> 5;

    __shared__ float wsum[K_DIM][8];
    __shared__ float bsh[K_DIM];
    __shared__ float dsh[K_DIM];

    float4 tv = make_float4(0.f, 0.f, 0.f, 0.f);
#pragma unroll
    for (int z = 0; z < SPLITK; ++z) {
        float4 a = reinterpret_cast<const float4*>(g_part[z])[c * H4 + t];
        tv.x += a.x; tv.y += a.y; tv.z += a.z; tv.w += a.w;
    }

    const float4* xp = reinterpret_cast<const float4*>(x) + (size_t)c * K_DIM * H4;

    // ---- Phase A: agreement b_inc[k] ----
#pragma unroll 4
    for (int k = 0; k < K_DIM; ++k) {
        float4 xv = __ldg(&xp[k * H4 + t]);
        float p = xv.x * tv.x + xv.y * tv.y + xv.z * tv.z + xv.w * tv.w;
#pragma unroll
        for (int off = 16; off; off >>= 1) p += __shfl_down_sync(0xffffffffu, p, off);
        if (lane == 0) wsum[k][wid] = p;
    }
    __syncthreads();

    if (t < K_DIM) {
        float bb = g_b[c * K_DIM + t];
#pragma unroll
        for (int wq = 0; wq < 8; ++wq) bb += wsum[t][wq];
        g_b[c * K_DIM + t] = bb;
        bsh[t] = bb;
    }
    __syncthreads();

    // ---- Softmax over K=64 in warp 0 ----
    if (t < 32) {
        float b0 = bsh[t], b1 = bsh[t + 32];
        float m = fmaxf(b0, b1);
#pragma unroll
        for (int off = 16; off; off >>= 1) m = fmaxf(m, __shfl_xor_sync(0xffffffffu, m, off));
        float e0 = expf(b0 - m), e1 = expf(b1 - m);
        float ss = e0 + e1;
#pragma unroll
        for (int off = 16; off; off >>= 1) ss += __shfl_xor_sync(0xffffffffu, ss, off);
        float inv = 1.0f / ss;
        dsh[t]      = e0 * inv;
        dsh[t + 32] = e1 * inv;
    }
    __syncthreads();

    // ---- Phase B: weighted sum (x re-read, L1/L2-resident) ----
    float4 acc = make_float4(0.f, 0.f, 0.f, 0.f);
#pragma unroll 4
    for (int k = 0; k < K_DIM; ++k) {
        const float dk = dsh[k];
        float4 xv = xp[k * H4 + t];
        acc.x += dk * xv.x; acc.y += dk * xv.y;
        acc.z += dk * xv.z; acc.w += dk * xv.w;
    }
    reinterpret_cast<float4*>(g_s)[c * H4 + t] = acc;
}

// -------------------------------------------------------------------------
// Launch: 3 routing iterations.
// -------------------------------------------------------------------------
extern "C" void kernel_launch(void* const* d_in, const int* in_sizes, int n_in,
                              void* d_out, int out_size) {
    const float* x = (const float*)d_in[0];   // [512,64,1024]
    const float* W = (const float*)d_in[1];   // [1024,1024]
    float* out = (float*)d_out;               // [512,1024]

    float *s_ptr, *c_ptr, *part_ptr;
    cudaGetSymbolAddress((void**)&s_ptr,    g_s);
    cudaGetSymbolAddress((void**)&c_ptr,    g_c);
    cudaGetSymbolAddress((void**)&part_ptr, g_part);

    const dim3 gemm_grid(H_DIM / 128, C_DIM / 128, SPLITK);  // (8, 4, 4) = 128 CTAs

    ws_uniform_kernel<<<C_DIM, 256>>>(x);

    for (int iter = 0; iter < 3; ++iter) {
        // c_hat = s @ W^T  (split-K partials)
        gemm_tc_kernel<1><<<gemm_grid, 128>>>(s_ptr, W, part_ptr);
        squash_kernel<<<C_DIM, 256>>>(iter == 2 ? out : c_ptr);

        if (iter < 2) {
            // t = c @ W  (split-K partials)
            gemm_tc_kernel<0><<<gemm_grid, 128>>>(c_ptr, W, part_ptr);
            fused_route_kernel<<<C_DIM, 256>>>(x);
        }
    }
}